// round 7
// baseline (speedup 1.0000x reference)
#include <cuda_runtime.h>
#include <cuda_bf16.h>
#include <math.h>
#include <stdint.h>

#define B_ROWS 65536
#define IN_DIM 256
#define G_DIM  512
#define W_DIM  512
#define LN_EPS 1e-5f

// ---------------- global scratch (device globals; no allocs) ----------------
__device__ __nv_bfloat16 g_xb[(size_t)B_ROWS * IN_DIM];    // inputs bf16
__device__ __nv_bfloat16 g_cb[(size_t)G_DIM * IN_DIM];     // centers bf16
__device__ __nv_bfloat16 g_wb[(size_t)W_DIM * G_DIM];      // W_mix bf16
__device__ __nv_bfloat16 g_scaled[(size_t)B_ROWS * G_DIM]; // RBF activations bf16
__device__ float g_xsq[B_ROWS];
__device__ float g_csq[G_DIM];
__device__ float g_s[G_DIM];

// ---------------- PTX helpers (sm_80+ subset; compute_103-safe) -------------
__device__ __forceinline__ uint32_t smem_cast(const void* p) {
    return (uint32_t)__cvta_generic_to_shared(p);
}
__device__ __forceinline__ void cp16(uint32_t dst, const void* src) {
    asm volatile("cp.async.cg.shared.global [%0], [%1], 16;" :: "r"(dst), "l"(src));
}
#define CP_COMMIT() asm volatile("cp.async.commit_group;" ::: "memory")
#define CP_WAIT(n)  asm volatile("cp.async.wait_group %0;" :: "n"(n) : "memory")

__device__ __forceinline__ void ldsm4(uint32_t* r, uint32_t addr) {
    asm volatile("ldmatrix.sync.aligned.m8n8.x4.shared.b16 {%0,%1,%2,%3}, [%4];"
                 : "=r"(r[0]), "=r"(r[1]), "=r"(r[2]), "=r"(r[3]) : "r"(addr));
}
__device__ __forceinline__ void mma_bf16(float* d, const uint32_t* a,
                                         uint32_t b0, uint32_t b1) {
    asm volatile(
        "mma.sync.aligned.m16n8k16.row.col.f32.bf16.bf16.f32 "
        "{%0,%1,%2,%3}, {%4,%5,%6,%7}, {%8,%9}, {%0,%1,%2,%3};"
        : "+f"(d[0]), "+f"(d[1]), "+f"(d[2]), "+f"(d[3])
        : "r"(a[0]), "r"(a[1]), "r"(a[2]), "r"(a[3]), "r"(b0), "r"(b1));
}

// ---------------- prep kernels ----------------------------------------------
__global__ __launch_bounds__(256) void conv_x(const float* __restrict__ x) {
    int row = blockIdx.x * 8 + (threadIdx.x >> 5);
    int lane = threadIdx.x & 31;
    const float* r = x + (size_t)row * IN_DIM;
    int k0 = lane * 8;
    float4 a0 = *(const float4*)(r + k0);
    float4 a1 = *(const float4*)(r + k0 + 4);
    float ss = a0.x*a0.x + a0.y*a0.y + a0.z*a0.z + a0.w*a0.w +
               a1.x*a1.x + a1.y*a1.y + a1.z*a1.z + a1.w*a1.w;
#pragma unroll
    for (int o = 16; o > 0; o >>= 1) ss += __shfl_xor_sync(0xffffffffu, ss, o);
    if (lane == 0) g_xsq[row] = ss;
    __nv_bfloat162 h0 = __floats2bfloat162_rn(a0.x, a0.y);
    __nv_bfloat162 h1 = __floats2bfloat162_rn(a0.z, a0.w);
    __nv_bfloat162 h2 = __floats2bfloat162_rn(a1.x, a1.y);
    __nv_bfloat162 h3 = __floats2bfloat162_rn(a1.z, a1.w);
    *(uint4*)(g_xb + (size_t)row * IN_DIM + k0) =
        make_uint4(*(uint32_t*)&h0, *(uint32_t*)&h1, *(uint32_t*)&h2, *(uint32_t*)&h3);
}

__global__ __launch_bounds__(256) void conv_c(const float* __restrict__ c,
                                              const float* __restrict__ ls) {
    int g = blockIdx.x * 8 + (threadIdx.x >> 5);
    int lane = threadIdx.x & 31;
    const float* r = c + (size_t)g * IN_DIM;
    int k0 = lane * 8;
    float4 a0 = *(const float4*)(r + k0);
    float4 a1 = *(const float4*)(r + k0 + 4);
    float ss = a0.x*a0.x + a0.y*a0.y + a0.z*a0.z + a0.w*a0.w +
               a1.x*a1.x + a1.y*a1.y + a1.z*a1.z + a1.w*a1.w;
#pragma unroll
    for (int o = 16; o > 0; o >>= 1) ss += __shfl_xor_sync(0xffffffffu, ss, o);
    if (lane == 0) { g_csq[g] = ss; g_s[g] = expf(ls[g]); }
    __nv_bfloat162 h0 = __floats2bfloat162_rn(a0.x, a0.y);
    __nv_bfloat162 h1 = __floats2bfloat162_rn(a0.z, a0.w);
    __nv_bfloat162 h2 = __floats2bfloat162_rn(a1.x, a1.y);
    __nv_bfloat162 h3 = __floats2bfloat162_rn(a1.z, a1.w);
    *(uint4*)(g_cb + (size_t)g * IN_DIM + k0) =
        make_uint4(*(uint32_t*)&h0, *(uint32_t*)&h1, *(uint32_t*)&h2, *(uint32_t*)&h3);
}

__global__ __launch_bounds__(256) void conv_w(const float* __restrict__ w) {
    int wr = blockIdx.x * 8 + (threadIdx.x >> 5);
    int lane = threadIdx.x & 31;
    const float* r = w + (size_t)wr * G_DIM;
#pragma unroll
    for (int part = 0; part < 2; part++) {
        int k0 = lane * 16 + part * 8;
        float4 a0 = *(const float4*)(r + k0);
        float4 a1 = *(const float4*)(r + k0 + 4);
        __nv_bfloat162 h0 = __floats2bfloat162_rn(a0.x, a0.y);
        __nv_bfloat162 h1 = __floats2bfloat162_rn(a0.z, a0.w);
        __nv_bfloat162 h2 = __floats2bfloat162_rn(a1.x, a1.y);
        __nv_bfloat162 h3 = __floats2bfloat162_rn(a1.z, a1.w);
        *(uint4*)(g_wb + (size_t)wr * G_DIM + k0) =
            make_uint4(*(uint32_t*)&h0, *(uint32_t*)&h1, *(uint32_t*)&h2, *(uint32_t*)&h3);
    }
}

// ---------------- GEMM1 (RBF): 128x128 tile, BK=64, 3 stages, frag dbuf ------
#define G1P 72
#define G1_STG ((128 + 128) * G1P)          // elems per stage (A then B)
#define G1_SMEM (3 * G1_STG * 2 + 1024)

__global__ __launch_bounds__(256, 2) void gemm1_rbf() {
    extern __shared__ __align__(16) __nv_bfloat16 sm[];
    float* s_c0 = (float*)(sm + 3 * G1_STG);
    float* s_c1 = s_c0 + 128;

    const int tid = threadIdx.x, lane = tid & 31, wid = tid >> 5;
    const int bm = blockIdx.y * 128, bn = blockIdx.x * 128;

    if (tid < 128) { s_c0[tid] = g_csq[bn + tid]; s_c1[tid] = g_s[bn + tid]; }

    const uint32_t sbase = smem_cast(sm);
    const int crow = tid >> 3, cc8 = (tid & 7) * 8;
    const __nv_bfloat16* pA = g_xb + (size_t)(bm + crow) * IN_DIM + cc8;
    const __nv_bfloat16* pB = g_cb + (size_t)(bn + crow) * IN_DIM + cc8;
    const uint32_t dA = sbase + (uint32_t)(crow * G1P + cc8) * 2;
    const uint32_t dB = dA + (uint32_t)(128 * G1P) * 2;

    auto load_chunk = [&](int kc, int stg) {
        const uint32_t so = (uint32_t)(stg * G1_STG) * 2;
#pragma unroll
        for (int i = 0; i < 4; i++) {
            cp16(dA + so + (uint32_t)(i * 32 * G1P) * 2, pA + kc * 64 + (size_t)(i * 32) * IN_DIM);
            cp16(dB + so + (uint32_t)(i * 32 * G1P) * 2, pB + kc * 64 + (size_t)(i * 32) * IN_DIM);
        }
    };

    const int m0 = (wid >> 2) * 64, n0 = (wid & 3) * 32;
    const int arow = lane & 15, acol = (lane >> 4) << 3;
    const int brow = (lane & 7) | ((lane & 16) >> 1), bcol = lane & 8;

    float acc[4][4][4] = {};
    uint32_t af[2][4][4], bfr[2][2][4];

    auto load_frags = [&](int stg, int kk, int b) {
        const uint32_t ab = sbase + (uint32_t)(stg * G1_STG) * 2;
        const uint32_t bb = ab + (uint32_t)(128 * G1P) * 2;
#pragma unroll
        for (int mf = 0; mf < 4; mf++)
            ldsm4(af[b][mf], ab + (uint32_t)((m0 + mf * 16 + arow) * G1P + kk * 16 + acol) * 2);
#pragma unroll
        for (int nh = 0; nh < 2; nh++)
            ldsm4(bfr[b][nh], bb + (uint32_t)((n0 + nh * 16 + brow) * G1P + kk * 16 + bcol) * 2);
    };
    auto do_mma = [&](int b) {
#pragma unroll
        for (int mf = 0; mf < 4; mf++)
#pragma unroll
            for (int nf = 0; nf < 4; nf++)
                mma_bf16(acc[mf][nf], af[b][mf],
                         bfr[b][nf >> 1][(nf & 1) * 2], bfr[b][nf >> 1][(nf & 1) * 2 + 1]);
    };

    load_chunk(0, 0); CP_COMMIT();
    load_chunk(1, 1); CP_COMMIT();
    CP_WAIT(1); __syncthreads();
    load_frags(0, 0, 0);

#pragma unroll 1
    for (int kc = 0; kc < 4; kc++) {
        if (kc + 2 < 4) load_chunk(kc + 2, (kc + 2) % 3);
        CP_COMMIT();
#pragma unroll
        for (int kk = 0; kk < 4; kk++) {
            const int cur = kk & 1;
            if (kk < 3) {
                load_frags(kc % 3, kk + 1, cur ^ 1);
            } else if (kc < 3) {
                CP_WAIT(1); __syncthreads();
                load_frags((kc + 1) % 3, 0, cur ^ 1);
            }
            do_mma(cur);
        }
    }

    // epilogue: exp(-(xq+cq-2acc)*s) -> g_scaled bf16
    const int erow = lane >> 2, ecol = (lane & 3) * 2;
#pragma unroll
    for (int mf = 0; mf < 4; mf++) {
        const int gm0 = bm + m0 + mf * 16 + erow;
        const float xq0 = g_xsq[gm0], xq1 = g_xsq[gm0 + 8];
#pragma unroll
        for (int nf = 0; nf < 4; nf++) {
            const int cl = n0 + nf * 8 + ecol;
            const int gc = bn + cl;
            const float cq0 = s_c0[cl], ss0 = s_c1[cl];
            const float cq1 = s_c0[cl + 1], ss1 = s_c1[cl + 1];
            float v00 = __expf((2.f * acc[mf][nf][0] - xq0 - cq0) * ss0);
            float v01 = __expf((2.f * acc[mf][nf][1] - xq0 - cq1) * ss1);
            float v10 = __expf((2.f * acc[mf][nf][2] - xq1 - cq0) * ss0);
            float v11 = __expf((2.f * acc[mf][nf][3] - xq1 - cq1) * ss1);
            __nv_bfloat162 h0 = __floats2bfloat162_rn(v00, v01);
            __nv_bfloat162 h1 = __floats2bfloat162_rn(v10, v11);
            *(uint32_t*)(g_scaled + (size_t)gm0 * G_DIM + gc) = *(uint32_t*)&h0;
            *(uint32_t*)(g_scaled + (size_t)(gm0 + 8) * G_DIM + gc) = *(uint32_t*)&h1;
        }
    }
}

// ---------------- GEMM2 + LayerNorm + tanh: 64x512 CTA, 512 thr, BK=64 -------
// 16 warps, warp tile 32x64 (wr = wid>>3 row-group, wc = wid&7 col-group).
// A (64 rows) and B (512 rows of W) streamed together, 2-stage.
#define G2P 72
#define G2_STG (576 * G2P)                       // elems per stage (A 64 + B 512)
#define G2_FLT ((size_t)(2 * G2_STG) * 2)        // byte offset of float section
#define G2_SMEM (G2_FLT + (512 * 3 + 64 * 8 * 2 + 128) * 4)

__global__ __launch_bounds__(512, 1) void gemm2_ln(const float* __restrict__ bias,
                                                   const float* __restrict__ gamma,
                                                   const float* __restrict__ beta,
                                                   float* __restrict__ out) {
    extern __shared__ __align__(16) __nv_bfloat16 sm[];
    float* vs_b  = (float*)((char*)sm + G2_FLT);
    float* vs_g  = vs_b + 512;
    float* vs_be = vs_g + 512;
    float* part_sum = vs_be + 512;   // [64 rows][8 col-groups]
    float* part_sq  = part_sum + 512;
    float* stats    = part_sq + 512; // [64][2] mean,rstd

    const int tid = threadIdx.x, lane = tid & 31, wid = tid >> 5;
    const int bm = blockIdx.x * 64;

    if (tid < 512) { vs_b[tid] = bias[tid]; vs_g[tid] = gamma[tid]; vs_be[tid] = beta[tid]; }

    const uint32_t sb0 = smem_cast(sm);
    const int crow = tid >> 3, cc8 = (tid & 7) * 8;   // 64 rows x 8 col-vecs

    auto load_chunk = [&](int kc, int stg) {
        const uint32_t base = sb0 + (uint32_t)(stg * G2_STG) * 2;
        // A: 64 rows (one cp16 per thread)
        cp16(base + (uint32_t)(crow * G2P + cc8) * 2,
             g_scaled + (size_t)(bm + crow) * G_DIM + kc * 64 + cc8);
        // B: 512 rows (8 cp16 per thread)
#pragma unroll
        for (int i = 0; i < 8; i++) {
            const int r = crow + i * 64;
            cp16(base + (uint32_t)((64 + r) * G2P + cc8) * 2,
                 g_wb + (size_t)r * G_DIM + kc * 64 + cc8);
        }
    };
    load_chunk(0, 0); CP_COMMIT();
    load_chunk(1, 1); CP_COMMIT();

    const int wr = wid >> 3, wc = wid & 7;            // 2 x 8 warp grid
    const int arow = lane & 15, acol = (lane >> 4) << 3;
    const int brow = (lane & 7) | ((lane & 16) >> 1), bcol = lane & 8;

    float acc[2][8][4] = {};

#pragma unroll 1
    for (int kc = 0; kc < 8; kc++) {
        CP_WAIT(1);
        __syncthreads();
        const uint32_t base = sb0 + (uint32_t)((kc & 1) * G2_STG) * 2;
#pragma unroll
        for (int kk = 0; kk < 4; kk++) {
            uint32_t af[2][4], bfr[4][4];
#pragma unroll
            for (int mf = 0; mf < 2; mf++)
                ldsm4(af[mf], base + (uint32_t)((wr * 32 + mf * 16 + arow) * G2P +
                                                kk * 16 + acol) * 2);
#pragma unroll
            for (int nh = 0; nh < 4; nh++)
                ldsm4(bfr[nh], base + (uint32_t)((64 + wc * 64 + nh * 16 + brow) * G2P +
                                                 kk * 16 + bcol) * 2);
#pragma unroll
            for (int mf = 0; mf < 2; mf++)
#pragma unroll
                for (int nf = 0; nf < 8; nf++)
                    mma_bf16(acc[mf][nf], af[mf],
                             bfr[nf >> 1][(nf & 1) * 2], bfr[nf >> 1][(nf & 1) * 2 + 1]);
        }
        __syncthreads();
        if (kc + 2 < 8) load_chunk(kc + 2, kc & 1);
        CP_COMMIT();
    }

    // ----- LayerNorm + tanh epilogue (fp32) -----
    const int ecol = (lane & 3) * 2;
#pragma unroll
    for (int mf = 0; mf < 2; mf++) {
        float s0 = 0.f, q0 = 0.f, s1 = 0.f, q1 = 0.f;
#pragma unroll
        for (int nf = 0; nf < 8; nf++) {
            const int c = wc * 64 + nf * 8 + ecol;
            float v00 = acc[mf][nf][0] + vs_b[c];
            float v01 = acc[mf][nf][1] + vs_b[c + 1];
            float v10 = acc[mf][nf][2] + vs_b[c];
            float v11 = acc[mf][nf][3] + vs_b[c + 1];
            acc[mf][nf][0] = v00; acc[mf][nf][1] = v01;
            acc[mf][nf][2] = v10; acc[mf][nf][3] = v11;
            s0 += v00 + v01; q0 += v00 * v00 + v01 * v01;
            s1 += v10 + v11; q1 += v10 * v10 + v11 * v11;
        }
#pragma unroll
        for (int o = 1; o <= 2; o <<= 1) {
            s0 += __shfl_xor_sync(0xffffffffu, s0, o);
            q0 += __shfl_xor_sync(0xffffffffu, q0, o);
            s1 += __shfl_xor_sync(0xffffffffu, s1, o);
            q1 += __shfl_xor_sync(0xffffffffu, q1, o);
        }
        if ((lane & 3) == 0) {
            const int r0 = wr * 32 + mf * 16 + (lane >> 2);
            part_sum[r0 * 8 + wc] = s0;       part_sq[r0 * 8 + wc] = q0;
            part_sum[(r0 + 8) * 8 + wc] = s1; part_sq[(r0 + 8) * 8 + wc] = q1;
        }
    }
    __syncthreads();
    if (tid < 64) {
        float s = 0.f, q = 0.f;
#pragma unroll
        for (int w = 0; w < 8; w++) { s += part_sum[tid * 8 + w]; q += part_sq[tid * 8 + w]; }
        const float mean = s * (1.0f / 512.0f);
        const float var  = q * (1.0f / 512.0f) - mean * mean;
        stats[tid * 2] = mean;
        stats[tid * 2 + 1] = rsqrtf(var + LN_EPS);
    }
    __syncthreads();

#pragma unroll
    for (int mf = 0; mf < 2; mf++) {
        const int r0 = wr * 32 + mf * 16 + (lane >> 2), r1 = r0 + 8;
        const float m0 = stats[r0 * 2], rs0 = stats[r0 * 2 + 1];
        const float m1 = stats[r1 * 2], rs1 = stats[r1 * 2 + 1];
#pragma unroll
        for (int nf = 0; nf < 8; nf++) {
            const int c = wc * 64 + nf * 8 + ecol;
            const float g0 = vs_g[c], g1 = vs_g[c + 1];
            const float be0 = vs_be[c], be1 = vs_be[c + 1];
            float2 y0 = make_float2(tanhf((acc[mf][nf][0] - m0) * rs0 * g0 + be0),
                                    tanhf((acc[mf][nf][1] - m0) * rs0 * g1 + be1));
            float2 y1 = make_float2(tanhf((acc[mf][nf][2] - m1) * rs1 * g0 + be0),
                                    tanhf((acc[mf][nf][3] - m1) * rs1 * g1 + be1));
            *(float2*)(out + (size_t)(bm + r0) * W_DIM + c) = y0;
            *(float2*)(out + (size_t)(bm + r1) * W_DIM + c) = y1;
        }
    }
}

// ---------------------------------------------------------------------------
extern "C" void kernel_launch(void* const* d_in, const int* in_sizes, int n_in,
                              void* d_out, int out_size) {
    const float* inputs     = (const float*)d_in[0];
    const float* centers    = (const float*)d_in[1];
    const float* log_scales = (const float*)d_in[2];
    const float* W_mix      = (const float*)d_in[3];
    const float* b_mix      = (const float*)d_in[4];
    const float* ln_gamma   = (const float*)d_in[5];
    const float* ln_beta    = (const float*)d_in[6];
    float* out = (float*)d_out;

    cudaFuncSetAttribute(gemm1_rbf, cudaFuncAttributeMaxDynamicSharedMemorySize, G1_SMEM);
    cudaFuncSetAttribute(gemm2_ln,  cudaFuncAttributeMaxDynamicSharedMemorySize, (int)G2_SMEM);

    conv_x<<<B_ROWS / 8, 256>>>(inputs);
    conv_c<<<G_DIM / 8, 256>>>(centers, log_scales);
    conv_w<<<W_DIM / 8, 256>>>(W_mix);
    gemm1_rbf<<<dim3(G_DIM / 128, B_ROWS / 128), 256, G1_SMEM>>>();
    gemm2_ln<<<B_ROWS / 64, 512, G2_SMEM>>>(b_mix, ln_gamma, ln_beta, out);
}

// round 8
// speedup vs baseline: 1.9889x; 1.9889x over previous
#include <cuda_runtime.h>
#include <cuda_bf16.h>
#include <math.h>
#include <stdint.h>

#define B_ROWS 65536
#define IN_DIM 256
#define G_DIM  512
#define W_DIM  512
#define LN_EPS 1e-5f

// ---------------- global scratch (device globals; no allocs) ----------------
__device__ __nv_bfloat16 g_xb[(size_t)B_ROWS * IN_DIM];    // inputs bf16
__device__ __nv_bfloat16 g_cb[(size_t)G_DIM * IN_DIM];     // centers bf16
__device__ __nv_bfloat16 g_wb[(size_t)W_DIM * G_DIM];      // W_mix bf16
__device__ __nv_bfloat16 g_scaled[(size_t)B_ROWS * G_DIM]; // RBF activations bf16
__device__ float g_xsq[B_ROWS];
__device__ float g_csq[G_DIM];
__device__ float g_s[G_DIM];
// nonzero flags: [m-tile of 64 rows][K-chunk of 64 cols] for g_scaled
__device__ int g_nz[(B_ROWS / 64) * 8];

// ---------------- PTX helpers (sm_80+ subset; compute_103-safe) -------------
__device__ __forceinline__ uint32_t smem_cast(const void* p) {
    return (uint32_t)__cvta_generic_to_shared(p);
}
__device__ __forceinline__ void cp16(uint32_t dst, const void* src) {
    asm volatile("cp.async.cg.shared.global [%0], [%1], 16;" :: "r"(dst), "l"(src));
}
#define CP_COMMIT() asm volatile("cp.async.commit_group;" ::: "memory")
#define CP_WAIT(n)  asm volatile("cp.async.wait_group %0;" :: "n"(n) : "memory")

__device__ __forceinline__ void ldsm4(uint32_t* r, uint32_t addr) {
    asm volatile("ldmatrix.sync.aligned.m8n8.x4.shared.b16 {%0,%1,%2,%3}, [%4];"
                 : "=r"(r[0]), "=r"(r[1]), "=r"(r[2]), "=r"(r[3]) : "r"(addr));
}
__device__ __forceinline__ void mma_bf16(float* d, const uint32_t* a,
                                         uint32_t b0, uint32_t b1) {
    asm volatile(
        "mma.sync.aligned.m16n8k16.row.col.f32.bf16.bf16.f32 "
        "{%0,%1,%2,%3}, {%4,%5,%6,%7}, {%8,%9}, {%0,%1,%2,%3};"
        : "+f"(d[0]), "+f"(d[1]), "+f"(d[2]), "+f"(d[3])
        : "r"(a[0]), "r"(a[1]), "r"(a[2]), "r"(a[3]), "r"(b0), "r"(b1));
}

// ---------------- flag reset --------------------------------------------------
__global__ void zero_nz() { g_nz[blockIdx.x * 1024 + threadIdx.x] = 0; }

// ---------------- prep kernels ----------------------------------------------
__global__ __launch_bounds__(256) void conv_x(const float* __restrict__ x) {
    int row = blockIdx.x * 8 + (threadIdx.x >> 5);
    int lane = threadIdx.x & 31;
    const float* r = x + (size_t)row * IN_DIM;
    int k0 = lane * 8;
    float4 a0 = *(const float4*)(r + k0);
    float4 a1 = *(const float4*)(r + k0 + 4);
    float ss = a0.x*a0.x + a0.y*a0.y + a0.z*a0.z + a0.w*a0.w +
               a1.x*a1.x + a1.y*a1.y + a1.z*a1.z + a1.w*a1.w;
#pragma unroll
    for (int o = 16; o > 0; o >>= 1) ss += __shfl_xor_sync(0xffffffffu, ss, o);
    if (lane == 0) g_xsq[row] = ss;
    __nv_bfloat162 h0 = __floats2bfloat162_rn(a0.x, a0.y);
    __nv_bfloat162 h1 = __floats2bfloat162_rn(a0.z, a0.w);
    __nv_bfloat162 h2 = __floats2bfloat162_rn(a1.x, a1.y);
    __nv_bfloat162 h3 = __floats2bfloat162_rn(a1.z, a1.w);
    *(uint4*)(g_xb + (size_t)row * IN_DIM + k0) =
        make_uint4(*(uint32_t*)&h0, *(uint32_t*)&h1, *(uint32_t*)&h2, *(uint32_t*)&h3);
}

__global__ __launch_bounds__(256) void conv_c(const float* __restrict__ c,
                                              const float* __restrict__ ls) {
    int g = blockIdx.x * 8 + (threadIdx.x >> 5);
    int lane = threadIdx.x & 31;
    const float* r = c + (size_t)g * IN_DIM;
    int k0 = lane * 8;
    float4 a0 = *(const float4*)(r + k0);
    float4 a1 = *(const float4*)(r + k0 + 4);
    float ss = a0.x*a0.x + a0.y*a0.y + a0.z*a0.z + a0.w*a0.w +
               a1.x*a1.x + a1.y*a1.y + a1.z*a1.z + a1.w*a1.w;
#pragma unroll
    for (int o = 16; o > 0; o >>= 1) ss += __shfl_xor_sync(0xffffffffu, ss, o);
    if (lane == 0) { g_csq[g] = ss; g_s[g] = expf(ls[g]); }
    __nv_bfloat162 h0 = __floats2bfloat162_rn(a0.x, a0.y);
    __nv_bfloat162 h1 = __floats2bfloat162_rn(a0.z, a0.w);
    __nv_bfloat162 h2 = __floats2bfloat162_rn(a1.x, a1.y);
    __nv_bfloat162 h3 = __floats2bfloat162_rn(a1.z, a1.w);
    *(uint4*)(g_cb + (size_t)g * IN_DIM + k0) =
        make_uint4(*(uint32_t*)&h0, *(uint32_t*)&h1, *(uint32_t*)&h2, *(uint32_t*)&h3);
}

__global__ __launch_bounds__(256) void conv_w(const float* __restrict__ w) {
    int wr = blockIdx.x * 8 + (threadIdx.x >> 5);
    int lane = threadIdx.x & 31;
    const float* r = w + (size_t)wr * G_DIM;
#pragma unroll
    for (int part = 0; part < 2; part++) {
        int k0 = lane * 16 + part * 8;
        float4 a0 = *(const float4*)(r + k0);
        float4 a1 = *(const float4*)(r + k0 + 4);
        __nv_bfloat162 h0 = __floats2bfloat162_rn(a0.x, a0.y);
        __nv_bfloat162 h1 = __floats2bfloat162_rn(a0.z, a0.w);
        __nv_bfloat162 h2 = __floats2bfloat162_rn(a1.x, a1.y);
        __nv_bfloat162 h3 = __floats2bfloat162_rn(a1.z, a1.w);
        *(uint4*)(g_wb + (size_t)wr * G_DIM + k0) =
            make_uint4(*(uint32_t*)&h0, *(uint32_t*)&h1, *(uint32_t*)&h2, *(uint32_t*)&h3);
    }
}

// ---------------- GEMM1 (RBF): 128x128 tile, BK=64, 3 stages, frag dbuf ------
#define G1P 72
#define G1_STG ((128 + 128) * G1P)          // elems per stage (A then B)
#define G1_SMEM (3 * G1_STG * 2 + 1024)

__global__ __launch_bounds__(256, 2) void gemm1_rbf() {
    extern __shared__ __align__(16) __nv_bfloat16 sm[];
    float* s_c0 = (float*)(sm + 3 * G1_STG);
    float* s_c1 = s_c0 + 128;

    const int tid = threadIdx.x, lane = tid & 31, wid = tid >> 5;
    const int bm = blockIdx.y * 128, bn = blockIdx.x * 128;

    if (tid < 128) { s_c0[tid] = g_csq[bn + tid]; s_c1[tid] = g_s[bn + tid]; }

    const uint32_t sbase = smem_cast(sm);
    const int crow = tid >> 3, cc8 = (tid & 7) * 8;
    const __nv_bfloat16* pA = g_xb + (size_t)(bm + crow) * IN_DIM + cc8;
    const __nv_bfloat16* pB = g_cb + (size_t)(bn + crow) * IN_DIM + cc8;
    const uint32_t dA = sbase + (uint32_t)(crow * G1P + cc8) * 2;
    const uint32_t dB = dA + (uint32_t)(128 * G1P) * 2;

    auto load_chunk = [&](int kc, int stg) {
        const uint32_t so = (uint32_t)(stg * G1_STG) * 2;
#pragma unroll
        for (int i = 0; i < 4; i++) {
            cp16(dA + so + (uint32_t)(i * 32 * G1P) * 2, pA + kc * 64 + (size_t)(i * 32) * IN_DIM);
            cp16(dB + so + (uint32_t)(i * 32 * G1P) * 2, pB + kc * 64 + (size_t)(i * 32) * IN_DIM);
        }
    };

    const int m0 = (wid >> 2) * 64, n0 = (wid & 3) * 32;
    const int arow = lane & 15, acol = (lane >> 4) << 3;
    const int brow = (lane & 7) | ((lane & 16) >> 1), bcol = lane & 8;

    float acc[4][4][4] = {};
    uint32_t af[2][4][4], bfr[2][2][4];

    auto load_frags = [&](int stg, int kk, int b) {
        const uint32_t ab = sbase + (uint32_t)(stg * G1_STG) * 2;
        const uint32_t bb = ab + (uint32_t)(128 * G1P) * 2;
#pragma unroll
        for (int mf = 0; mf < 4; mf++)
            ldsm4(af[b][mf], ab + (uint32_t)((m0 + mf * 16 + arow) * G1P + kk * 16 + acol) * 2);
#pragma unroll
        for (int nh = 0; nh < 2; nh++)
            ldsm4(bfr[b][nh], bb + (uint32_t)((n0 + nh * 16 + brow) * G1P + kk * 16 + bcol) * 2);
    };
    auto do_mma = [&](int b) {
#pragma unroll
        for (int mf = 0; mf < 4; mf++)
#pragma unroll
            for (int nf = 0; nf < 4; nf++)
                mma_bf16(acc[mf][nf], af[b][mf],
                         bfr[b][nf >> 1][(nf & 1) * 2], bfr[b][nf >> 1][(nf & 1) * 2 + 1]);
    };

    load_chunk(0, 0); CP_COMMIT();
    load_chunk(1, 1); CP_COMMIT();
    CP_WAIT(1); __syncthreads();
    load_frags(0, 0, 0);

#pragma unroll 1
    for (int kc = 0; kc < 4; kc++) {
        if (kc + 2 < 4) load_chunk(kc + 2, (kc + 2) % 3);
        CP_COMMIT();
#pragma unroll
        for (int kk = 0; kk < 4; kk++) {
            const int cur = kk & 1;
            if (kk < 3) {
                load_frags(kc % 3, kk + 1, cur ^ 1);
            } else if (kc < 3) {
                CP_WAIT(1); __syncthreads();
                load_frags((kc + 1) % 3, 0, cur ^ 1);
            }
            do_mma(cur);
        }
    }

    // epilogue: exp(-(xq+cq-2acc)*s) -> g_scaled bf16 (predicated stores),
    // plus per-warp nonzero flag for block-sparse GEMM2.
    const int erow = lane >> 2, ecol = (lane & 3) * 2;
    uint32_t nzu = 0;
#pragma unroll
    for (int mf = 0; mf < 4; mf++) {
        const int gm0 = bm + m0 + mf * 16 + erow;
        const float xq0 = g_xsq[gm0], xq1 = g_xsq[gm0 + 8];
#pragma unroll
        for (int nf = 0; nf < 4; nf++) {
            const int cl = n0 + nf * 8 + ecol;
            const int gc = bn + cl;
            const float cq0 = s_c0[cl], ss0 = s_c1[cl];
            const float cq1 = s_c0[cl + 1], ss1 = s_c1[cl + 1];
            float v00 = __expf((2.f * acc[mf][nf][0] - xq0 - cq0) * ss0);
            float v01 = __expf((2.f * acc[mf][nf][1] - xq0 - cq1) * ss1);
            float v10 = __expf((2.f * acc[mf][nf][2] - xq1 - cq0) * ss0);
            float v11 = __expf((2.f * acc[mf][nf][3] - xq1 - cq1) * ss1);
            __nv_bfloat162 h0 = __floats2bfloat162_rn(v00, v01);
            __nv_bfloat162 h1 = __floats2bfloat162_rn(v10, v11);
            const uint32_t p0 = *(uint32_t*)&h0, p1 = *(uint32_t*)&h1;
            nzu |= p0 | p1;
            // zero positions stay zero (device globals are zero-initialized,
            // and for fixed inputs positions never flip nonzero->zero)
            if (p0) *(uint32_t*)(g_scaled + (size_t)gm0 * G_DIM + gc) = p0;
            if (p1) *(uint32_t*)(g_scaled + (size_t)(gm0 + 8) * G_DIM + gc) = p1;
        }
    }
    const uint32_t any = __reduce_or_sync(0xffffffffu, nzu);
    if (lane == 0 && any)
        atomicOr(&g_nz[((bm + m0) >> 6) * 8 + ((bn + n0) >> 6)], 1);
}

// ---------------- GEMM2 + LayerNorm + tanh: 64x512 CTA, 512 thr, BK=64 -------
// Block-sparse over K: chunks whose scaled-block is all-zero are skipped.
#define G2P 72
#define G2_STG (576 * G2P)                       // elems per stage (A 64 + B 512)
#define G2_FLT ((size_t)(2 * G2_STG) * 2)        // byte offset of float section
#define G2_SMEM (G2_FLT + (512 * 3 + 64 * 8 * 2 + 128 + 8) * 4)

__global__ __launch_bounds__(512, 1) void gemm2_ln(const float* __restrict__ bias,
                                                   const float* __restrict__ gamma,
                                                   const float* __restrict__ beta,
                                                   float* __restrict__ out) {
    extern __shared__ __align__(16) __nv_bfloat16 sm[];
    float* vs_b  = (float*)((char*)sm + G2_FLT);
    float* vs_g  = vs_b + 512;
    float* vs_be = vs_g + 512;
    float* part_sum = vs_be + 512;   // [64 rows][8 col-groups]
    float* part_sq  = part_sum + 512;
    float* stats    = part_sq + 512; // [64][2] mean,rstd
    int*   s_nz     = (int*)(stats + 128);

    const int tid = threadIdx.x, lane = tid & 31, wid = tid >> 5;
    const int bm = blockIdx.x * 64;

    if (tid < 512) { vs_b[tid] = bias[tid]; vs_g[tid] = gamma[tid]; vs_be[tid] = beta[tid]; }
    if (tid < 8) s_nz[tid] = g_nz[(bm >> 6) * 8 + tid];
    __syncthreads();

    int act[8], nact = 0;
#pragma unroll
    for (int k = 0; k < 8; k++) if (s_nz[k]) act[nact++] = k;

    const uint32_t sb0 = smem_cast(sm);
    const int crow = tid >> 3, cc8 = (tid & 7) * 8;

    auto load_chunk = [&](int kc, int stg) {
        const uint32_t base = sb0 + (uint32_t)(stg * G2_STG) * 2;
        cp16(base + (uint32_t)(crow * G2P + cc8) * 2,
             g_scaled + (size_t)(bm + crow) * G_DIM + kc * 64 + cc8);
#pragma unroll
        for (int i = 0; i < 8; i++) {
            const int r = crow + i * 64;
            cp16(base + (uint32_t)((64 + r) * G2P + cc8) * 2,
                 g_wb + (size_t)r * G_DIM + kc * 64 + cc8);
        }
    };

    const int wr = wid >> 3, wc = wid & 7;            // 2 x 8 warp grid
    const int arow = lane & 15, acol = (lane >> 4) << 3;
    const int brow = (lane & 7) | ((lane & 16) >> 1), bcol = lane & 8;

    float acc[2][8][4] = {};

    if (nact > 0) {
        load_chunk(act[0], 0); CP_COMMIT();
        if (nact > 1) { load_chunk(act[1], 1); CP_COMMIT(); }

#pragma unroll 1
        for (int i = 0; i < nact; i++) {
            if (i + 1 < nact) { CP_WAIT(1); } else { CP_WAIT(0); }
            __syncthreads();
            const uint32_t base = sb0 + (uint32_t)((i & 1) * G2_STG) * 2;
#pragma unroll
            for (int kk = 0; kk < 4; kk++) {
                uint32_t af[2][4], bfr[4][4];
#pragma unroll
                for (int mf = 0; mf < 2; mf++)
                    ldsm4(af[mf], base + (uint32_t)((wr * 32 + mf * 16 + arow) * G2P +
                                                    kk * 16 + acol) * 2);
#pragma unroll
                for (int nh = 0; nh < 4; nh++)
                    ldsm4(bfr[nh], base + (uint32_t)((64 + wc * 64 + nh * 16 + brow) * G2P +
                                                     kk * 16 + bcol) * 2);
#pragma unroll
                for (int mf = 0; mf < 2; mf++)
#pragma unroll
                    for (int nf = 0; nf < 8; nf++)
                        mma_bf16(acc[mf][nf], af[mf],
                                 bfr[nf >> 1][(nf & 1) * 2], bfr[nf >> 1][(nf & 1) * 2 + 1]);
            }
            __syncthreads();
            if (i + 2 < nact) { load_chunk(act[i + 2], i & 1); CP_COMMIT(); }
        }
    }

    // ----- LayerNorm + tanh epilogue (fp32) -----
    const int ecol = (lane & 3) * 2;
#pragma unroll
    for (int mf = 0; mf < 2; mf++) {
        float s0 = 0.f, q0 = 0.f, s1 = 0.f, q1 = 0.f;
#pragma unroll
        for (int nf = 0; nf < 8; nf++) {
            const int c = wc * 64 + nf * 8 + ecol;
            float v00 = acc[mf][nf][0] + vs_b[c];
            float v01 = acc[mf][nf][1] + vs_b[c + 1];
            float v10 = acc[mf][nf][2] + vs_b[c];
            float v11 = acc[mf][nf][3] + vs_b[c + 1];
            acc[mf][nf][0] = v00; acc[mf][nf][1] = v01;
            acc[mf][nf][2] = v10; acc[mf][nf][3] = v11;
            s0 += v00 + v01; q0 += v00 * v00 + v01 * v01;
            s1 += v10 + v11; q1 += v10 * v10 + v11 * v11;
        }
#pragma unroll
        for (int o = 1; o <= 2; o <<= 1) {
            s0 += __shfl_xor_sync(0xffffffffu, s0, o);
            q0 += __shfl_xor_sync(0xffffffffu, q0, o);
            s1 += __shfl_xor_sync(0xffffffffu, s1, o);
            q1 += __shfl_xor_sync(0xffffffffu, q1, o);
        }
        if ((lane & 3) == 0) {
            const int r0 = wr * 32 + mf * 16 + (lane >> 2);
            part_sum[r0 * 8 + wc] = s0;       part_sq[r0 * 8 + wc] = q0;
            part_sum[(r0 + 8) * 8 + wc] = s1; part_sq[(r0 + 8) * 8 + wc] = q1;
        }
    }
    __syncthreads();
    if (tid < 64) {
        float s = 0.f, q = 0.f;
#pragma unroll
        for (int w = 0; w < 8; w++) { s += part_sum[tid * 8 + w]; q += part_sq[tid * 8 + w]; }
        const float mean = s * (1.0f / 512.0f);
        const float var  = q * (1.0f / 512.0f) - mean * mean;
        stats[tid * 2] = mean;
        stats[tid * 2 + 1] = rsqrtf(var + LN_EPS);
    }
    __syncthreads();

#pragma unroll
    for (int mf = 0; mf < 2; mf++) {
        const int r0 = wr * 32 + mf * 16 + (lane >> 2), r1 = r0 + 8;
        const float m0 = stats[r0 * 2], rs0 = stats[r0 * 2 + 1];
        const float m1 = stats[r1 * 2], rs1 = stats[r1 * 2 + 1];
#pragma unroll
        for (int nf = 0; nf < 8; nf++) {
            const int c = wc * 64 + nf * 8 + ecol;
            const float g0 = vs_g[c], g1 = vs_g[c + 1];
            const float be0 = vs_be[c], be1 = vs_be[c + 1];
            float2 y0 = make_float2(tanhf((acc[mf][nf][0] - m0) * rs0 * g0 + be0),
                                    tanhf((acc[mf][nf][1] - m0) * rs0 * g1 + be1));
            float2 y1 = make_float2(tanhf((acc[mf][nf][2] - m1) * rs1 * g0 + be0),
                                    tanhf((acc[mf][nf][3] - m1) * rs1 * g1 + be1));
            *(float2*)(out + (size_t)(bm + r0) * W_DIM + c) = y0;
            *(float2*)(out + (size_t)(bm + r1) * W_DIM + c) = y1;
        }
    }
}

// ---------------------------------------------------------------------------
extern "C" void kernel_launch(void* const* d_in, const int* in_sizes, int n_in,
                              void* d_out, int out_size) {
    const float* inputs     = (const float*)d_in[0];
    const float* centers    = (const float*)d_in[1];
    const float* log_scales = (const float*)d_in[2];
    const float* W_mix      = (const float*)d_in[3];
    const float* b_mix      = (const float*)d_in[4];
    const float* ln_gamma   = (const float*)d_in[5];
    const float* ln_beta    = (const float*)d_in[6];
    float* out = (float*)d_out;

    cudaFuncSetAttribute(gemm1_rbf, cudaFuncAttributeMaxDynamicSharedMemorySize, G1_SMEM);
    cudaFuncSetAttribute(gemm2_ln,  cudaFuncAttributeMaxDynamicSharedMemorySize, (int)G2_SMEM);

    zero_nz<<<(B_ROWS / 64) * 8 / 1024, 1024>>>();
    conv_x<<<B_ROWS / 8, 256>>>(inputs);
    conv_c<<<G_DIM / 8, 256>>>(centers, log_scales);
    conv_w<<<W_DIM / 8, 256>>>(W_mix);
    gemm1_rbf<<<dim3(G_DIM / 128, B_ROWS / 128), 256, G1_SMEM>>>();
    gemm2_ln<<<B_ROWS / 64, 512, G2_SMEM>>>(b_mix, ln_gamma, ln_beta, out);
}

// round 9
// speedup vs baseline: 2.0508x; 1.0311x over previous
#include <cuda_runtime.h>
#include <cuda_bf16.h>
#include <cuda_fp8.h>
#include <math.h>
#include <stdint.h>

#define B_ROWS 65536
#define IN_DIM 256
#define G_DIM  512
#define W_DIM  512
#define LN_EPS 1e-5f

// ---------------- global scratch (device globals; no allocs) ----------------
__device__ uint8_t g_x8[(size_t)B_ROWS * IN_DIM];          // inputs e4m3
__device__ uint8_t g_c8[(size_t)G_DIM * IN_DIM];           // centers e4m3
__device__ __nv_bfloat16 g_wb[(size_t)W_DIM * G_DIM];      // W_mix bf16
__device__ __nv_bfloat16 g_scaled[(size_t)B_ROWS * G_DIM]; // RBF activations bf16
__device__ float g_xsq[B_ROWS];
__device__ float g_csq[G_DIM];
__device__ float g_s[G_DIM];
// nonzero flags: [m-tile of 64 rows][K-chunk of 64 cols] for g_scaled
__device__ int g_nz[(B_ROWS / 64) * 8];

// ---------------- PTX helpers (sm_80/89+ subset; compute_103-safe) ----------
__device__ __forceinline__ uint32_t smem_cast(const void* p) {
    return (uint32_t)__cvta_generic_to_shared(p);
}
__device__ __forceinline__ void cp16(uint32_t dst, const void* src) {
    asm volatile("cp.async.cg.shared.global [%0], [%1], 16;" :: "r"(dst), "l"(src));
}
#define CP_COMMIT() asm volatile("cp.async.commit_group;" ::: "memory")
#define CP_WAIT(n)  asm volatile("cp.async.wait_group %0;" :: "n"(n) : "memory")

__device__ __forceinline__ void ldsm4(uint32_t* r, uint32_t addr) {
    asm volatile("ldmatrix.sync.aligned.m8n8.x4.shared.b16 {%0,%1,%2,%3}, [%4];"
                 : "=r"(r[0]), "=r"(r[1]), "=r"(r[2]), "=r"(r[3]) : "r"(addr));
}
__device__ __forceinline__ void mma_bf16(float* d, const uint32_t* a,
                                         uint32_t b0, uint32_t b1) {
    asm volatile(
        "mma.sync.aligned.m16n8k16.row.col.f32.bf16.bf16.f32 "
        "{%0,%1,%2,%3}, {%4,%5,%6,%7}, {%8,%9}, {%0,%1,%2,%3};"
        : "+f"(d[0]), "+f"(d[1]), "+f"(d[2]), "+f"(d[3])
        : "r"(a[0]), "r"(a[1]), "r"(a[2]), "r"(a[3]), "r"(b0), "r"(b1));
}
__device__ __forceinline__ void mma_fp8(float* d, const uint32_t* a,
                                        uint32_t b0, uint32_t b1) {
    asm volatile(
        "mma.sync.aligned.m16n8k32.row.col.f32.e4m3.e4m3.f32 "
        "{%0,%1,%2,%3}, {%4,%5,%6,%7}, {%8,%9}, {%0,%1,%2,%3};"
        : "+f"(d[0]), "+f"(d[1]), "+f"(d[2]), "+f"(d[3])
        : "r"(a[0]), "r"(a[1]), "r"(a[2]), "r"(a[3]), "r"(b0), "r"(b1));
}

__device__ __forceinline__ ushort4 cvt8_e4m3(float4 a0, float4 a1) {
    ushort4 u;
    u.x = __nv_cvt_float2_to_fp8x2(make_float2(a0.x, a0.y), __NV_SATFINITE, __NV_E4M3);
    u.y = __nv_cvt_float2_to_fp8x2(make_float2(a0.z, a0.w), __NV_SATFINITE, __NV_E4M3);
    u.z = __nv_cvt_float2_to_fp8x2(make_float2(a1.x, a1.y), __NV_SATFINITE, __NV_E4M3);
    u.w = __nv_cvt_float2_to_fp8x2(make_float2(a1.z, a1.w), __NV_SATFINITE, __NV_E4M3);
    return u;
}

// ---------------- prep kernels ----------------------------------------------
// warp per row: row-sumsq (exact fp32) + fp32 -> e4m3 convert
__global__ __launch_bounds__(256) void conv_x(const float* __restrict__ x) {
    int row = blockIdx.x * 8 + (threadIdx.x >> 5);
    int lane = threadIdx.x & 31;
    const float* r = x + (size_t)row * IN_DIM;
    int k0 = lane * 8;
    float4 a0 = *(const float4*)(r + k0);
    float4 a1 = *(const float4*)(r + k0 + 4);
    float ss = a0.x*a0.x + a0.y*a0.y + a0.z*a0.z + a0.w*a0.w +
               a1.x*a1.x + a1.y*a1.y + a1.z*a1.z + a1.w*a1.w;
#pragma unroll
    for (int o = 16; o > 0; o >>= 1) ss += __shfl_xor_sync(0xffffffffu, ss, o);
    if (lane == 0) g_xsq[row] = ss;
    *(ushort4*)(g_x8 + (size_t)row * IN_DIM + k0) = cvt8_e4m3(a0, a1);
}

// merged: centers->e4m3 + csq + s (blocks 0..63), W->bf16 (blocks 64..127),
// and g_nz reset (first 8192 global threads).
__global__ __launch_bounds__(256) void conv_cw(const float* __restrict__ c,
                                               const float* __restrict__ ls,
                                               const float* __restrict__ w) {
    const int gtid = blockIdx.x * 256 + threadIdx.x;
    if (gtid < (B_ROWS / 64) * 8) g_nz[gtid] = 0;

    int lane = threadIdx.x & 31;
    if (blockIdx.x < 64) {
        int g = blockIdx.x * 8 + (threadIdx.x >> 5);
        const float* r = c + (size_t)g * IN_DIM;
        int k0 = lane * 8;
        float4 a0 = *(const float4*)(r + k0);
        float4 a1 = *(const float4*)(r + k0 + 4);
        float ss = a0.x*a0.x + a0.y*a0.y + a0.z*a0.z + a0.w*a0.w +
                   a1.x*a1.x + a1.y*a1.y + a1.z*a1.z + a1.w*a1.w;
#pragma unroll
        for (int o = 16; o > 0; o >>= 1) ss += __shfl_xor_sync(0xffffffffu, ss, o);
        if (lane == 0) { g_csq[g] = ss; g_s[g] = expf(ls[g]); }
        *(ushort4*)(g_c8 + (size_t)g * IN_DIM + k0) = cvt8_e4m3(a0, a1);
    } else {
        int wr = (blockIdx.x - 64) * 8 + (threadIdx.x >> 5);
        const float* r = w + (size_t)wr * G_DIM;
#pragma unroll
        for (int part = 0; part < 2; part++) {
            int k0 = lane * 16 + part * 8;
            float4 a0 = *(const float4*)(r + k0);
            float4 a1 = *(const float4*)(r + k0 + 4);
            __nv_bfloat162 h0 = __floats2bfloat162_rn(a0.x, a0.y);
            __nv_bfloat162 h1 = __floats2bfloat162_rn(a0.z, a0.w);
            __nv_bfloat162 h2 = __floats2bfloat162_rn(a1.x, a1.y);
            __nv_bfloat162 h3 = __floats2bfloat162_rn(a1.z, a1.w);
            *(uint4*)(g_wb + (size_t)wr * G_DIM + k0) =
                make_uint4(*(uint32_t*)&h0, *(uint32_t*)&h1, *(uint32_t*)&h2, *(uint32_t*)&h3);
        }
    }
}

// ---------------- GEMM1 (RBF, e4m3): 128x128 tile, K=256 resident ------------
// Whole A (128x256B) + B (128x256B) fp8 tile pair loaded once; 8 k32 MMA steps.
#define P1 272                            // smem row pitch in bytes (256 + 16 pad)
#define G1_B   (128 * P1)                 // B tile smem byte offset
#define G1_SMEM (2 * 128 * P1 + 1024)     // + consts

__global__ __launch_bounds__(256, 2) void gemm1_rbf() {
    extern __shared__ __align__(16) uint8_t sm[];
    float* s_c0 = (float*)(sm + 2 * 128 * P1);
    float* s_c1 = s_c0 + 128;

    const int tid = threadIdx.x, lane = tid & 31, wid = tid >> 5;
    const int bm = blockIdx.y * 128, bn = blockIdx.x * 128;

    if (tid < 128) { s_c0[tid] = g_csq[bn + tid]; s_c1[tid] = g_s[bn + tid]; }

    const uint32_t sbase = smem_cast(sm);
    // load A+B fp8 tiles (16 cp16/row-of-256B; 8 per thread per tile)
#pragma unroll
    for (int i = 0; i < 8; i++) {
        const int v = i * 256 + tid;
        const int row = v >> 4, cb = (v & 15) * 16;
        cp16(sbase + (uint32_t)(row * P1 + cb), g_x8 + (size_t)(bm + row) * IN_DIM + cb);
    }
#pragma unroll
    for (int i = 0; i < 8; i++) {
        const int v = i * 256 + tid;
        const int row = v >> 4, cb = (v & 15) * 16;
        cp16(sbase + (uint32_t)(G1_B + row * P1 + cb), g_c8 + (size_t)(bn + row) * IN_DIM + cb);
    }
    CP_COMMIT();
    CP_WAIT(0);
    __syncthreads();

    const int m0 = (wid >> 2) * 64, n0 = (wid & 3) * 32;
    const int arow = lane & 15, acolb = (lane >> 4) * 16;              // byte col
    const int brow = (lane & 7) | ((lane & 16) >> 1), bcolb = (lane & 8) * 2;

    float acc[4][4][4] = {};
    uint32_t af[2][4][4], bfr[2][2][4];

    auto load_frags = [&](int kk, int b) {
#pragma unroll
        for (int mf = 0; mf < 4; mf++)
            ldsm4(af[b][mf], sbase + (uint32_t)((m0 + mf * 16 + arow) * P1 + kk * 32 + acolb));
#pragma unroll
        for (int nh = 0; nh < 2; nh++)
            ldsm4(bfr[b][nh], sbase + (uint32_t)(G1_B + (n0 + nh * 16 + brow) * P1 + kk * 32 + bcolb));
    };
    auto do_mma = [&](int b) {
#pragma unroll
        for (int mf = 0; mf < 4; mf++)
#pragma unroll
            for (int nf = 0; nf < 4; nf++)
                mma_fp8(acc[mf][nf], af[b][mf],
                        bfr[b][nf >> 1][(nf & 1) * 2], bfr[b][nf >> 1][(nf & 1) * 2 + 1]);
    };

    load_frags(0, 0);
#pragma unroll
    for (int kk = 0; kk < 8; kk++) {
        if (kk < 7) load_frags(kk + 1, (kk + 1) & 1);
        do_mma(kk & 1);
    }

    // epilogue: exp(-(xq+cq-2acc)*s) -> g_scaled bf16 (predicated stores) + flags
    const int erow = lane >> 2, ecol = (lane & 3) * 2;
    uint32_t nzu = 0;
#pragma unroll
    for (int mf = 0; mf < 4; mf++) {
        const int gm0 = bm + m0 + mf * 16 + erow;
        const float xq0 = g_xsq[gm0], xq1 = g_xsq[gm0 + 8];
#pragma unroll
        for (int nf = 0; nf < 4; nf++) {
            const int cl = n0 + nf * 8 + ecol;
            const int gc = bn + cl;
            const float cq0 = s_c0[cl], ss0 = s_c1[cl];
            const float cq1 = s_c0[cl + 1], ss1 = s_c1[cl + 1];
            float v00 = __expf((2.f * acc[mf][nf][0] - xq0 - cq0) * ss0);
            float v01 = __expf((2.f * acc[mf][nf][1] - xq0 - cq1) * ss1);
            float v10 = __expf((2.f * acc[mf][nf][2] - xq1 - cq0) * ss0);
            float v11 = __expf((2.f * acc[mf][nf][3] - xq1 - cq1) * ss1);
            __nv_bfloat162 h0 = __floats2bfloat162_rn(v00, v01);
            __nv_bfloat162 h1 = __floats2bfloat162_rn(v10, v11);
            const uint32_t p0 = *(uint32_t*)&h0, p1 = *(uint32_t*)&h1;
            nzu |= p0 | p1;
            if (p0) *(uint32_t*)(g_scaled + (size_t)gm0 * G_DIM + gc) = p0;
            if (p1) *(uint32_t*)(g_scaled + (size_t)(gm0 + 8) * G_DIM + gc) = p1;
        }
    }
    const uint32_t any = __reduce_or_sync(0xffffffffu, nzu);
    if (lane == 0 && any)
        atomicOr(&g_nz[((bm + m0) >> 6) * 8 + ((bn + n0) >> 6)], 1);
}

// ---------------- GEMM2 + LayerNorm + tanh: 64x512 CTA, 512 thr, BK=64 -------
// Block-sparse over K: chunks whose scaled-block is all-zero are skipped.
#define G2P 72
#define G2_STG (576 * G2P)                       // elems per stage (A 64 + B 512)
#define G2_FLT ((size_t)(2 * G2_STG) * 2)        // byte offset of float section
#define G2_SMEM (G2_FLT + (512 * 3 + 64 * 8 * 2 + 128 + 8) * 4)

__global__ __launch_bounds__(512, 1) void gemm2_ln(const float* __restrict__ bias,
                                                   const float* __restrict__ gamma,
                                                   const float* __restrict__ beta,
                                                   float* __restrict__ out) {
    extern __shared__ __align__(16) __nv_bfloat16 smh[];
    float* vs_b  = (float*)((char*)smh + G2_FLT);
    float* vs_g  = vs_b + 512;
    float* vs_be = vs_g + 512;
    float* part_sum = vs_be + 512;   // [64 rows][8 col-groups]
    float* part_sq  = part_sum + 512;
    float* stats    = part_sq + 512; // [64][2] mean,rstd
    int*   s_nz     = (int*)(stats + 128);

    const int tid = threadIdx.x, lane = tid & 31, wid = tid >> 5;
    const int bm = blockIdx.x * 64;

    if (tid < 512) { vs_b[tid] = bias[tid]; vs_g[tid] = gamma[tid]; vs_be[tid] = beta[tid]; }
    if (tid < 8) s_nz[tid] = g_nz[(bm >> 6) * 8 + tid];
    __syncthreads();

    int act[8], nact = 0;
#pragma unroll
    for (int k = 0; k < 8; k++) if (s_nz[k]) act[nact++] = k;

    const uint32_t sb0 = smem_cast(smh);
    const int crow = tid >> 3, cc8 = (tid & 7) * 8;

    auto load_chunk = [&](int kc, int stg) {
        const uint32_t base = sb0 + (uint32_t)(stg * G2_STG) * 2;
        cp16(base + (uint32_t)(crow * G2P + cc8) * 2,
             g_scaled + (size_t)(bm + crow) * G_DIM + kc * 64 + cc8);
#pragma unroll
        for (int i = 0; i < 8; i++) {
            const int r = crow + i * 64;
            cp16(base + (uint32_t)((64 + r) * G2P + cc8) * 2,
                 g_wb + (size_t)r * G_DIM + kc * 64 + cc8);
        }
    };

    const int wr = wid >> 3, wc = wid & 7;            // 2 x 8 warp grid
    const int arow = lane & 15, acol = (lane >> 4) << 3;
    const int brow = (lane & 7) | ((lane & 16) >> 1), bcol = lane & 8;

    float acc[2][8][4] = {};

    if (nact > 0) {
        load_chunk(act[0], 0); CP_COMMIT();
        if (nact > 1) { load_chunk(act[1], 1); CP_COMMIT(); }

#pragma unroll 1
        for (int i = 0; i < nact; i++) {
            if (i + 1 < nact) { CP_WAIT(1); } else { CP_WAIT(0); }
            __syncthreads();
            const uint32_t base = sb0 + (uint32_t)((i & 1) * G2_STG) * 2;
#pragma unroll
            for (int kk = 0; kk < 4; kk++) {
                uint32_t af[2][4], bfr[4][4];
#pragma unroll
                for (int mf = 0; mf < 2; mf++)
                    ldsm4(af[mf], base + (uint32_t)((wr * 32 + mf * 16 + arow) * G2P +
                                                    kk * 16 + acol) * 2);
#pragma unroll
                for (int nh = 0; nh < 4; nh++)
                    ldsm4(bfr[nh], base + (uint32_t)((64 + wc * 64 + nh * 16 + brow) * G2P +
                                                     kk * 16 + bcol) * 2);
#pragma unroll
                for (int mf = 0; mf < 2; mf++)
#pragma unroll
                    for (int nf = 0; nf < 8; nf++)
                        mma_bf16(acc[mf][nf], af[mf],
                                 bfr[nf >> 1][(nf & 1) * 2], bfr[nf >> 1][(nf & 1) * 2 + 1]);
            }
            __syncthreads();
            if (i + 2 < nact) { load_chunk(act[i + 2], i & 1); CP_COMMIT(); }
        }
    }

    // ----- LayerNorm + tanh epilogue (fp32) -----
    const int ecol = (lane & 3) * 2;
#pragma unroll
    for (int mf = 0; mf < 2; mf++) {
        float s0 = 0.f, q0 = 0.f, s1 = 0.f, q1 = 0.f;
#pragma unroll
        for (int nf = 0; nf < 8; nf++) {
            const int c = wc * 64 + nf * 8 + ecol;
            float v00 = acc[mf][nf][0] + vs_b[c];
            float v01 = acc[mf][nf][1] + vs_b[c + 1];
            float v10 = acc[mf][nf][2] + vs_b[c];
            float v11 = acc[mf][nf][3] + vs_b[c + 1];
            acc[mf][nf][0] = v00; acc[mf][nf][1] = v01;
            acc[mf][nf][2] = v10; acc[mf][nf][3] = v11;
            s0 += v00 + v01; q0 += v00 * v00 + v01 * v01;
            s1 += v10 + v11; q1 += v10 * v10 + v11 * v11;
        }
#pragma unroll
        for (int o = 1; o <= 2; o <<= 1) {
            s0 += __shfl_xor_sync(0xffffffffu, s0, o);
            q0 += __shfl_xor_sync(0xffffffffu, q0, o);
            s1 += __shfl_xor_sync(0xffffffffu, s1, o);
            q1 += __shfl_xor_sync(0xffffffffu, q1, o);
        }
        if ((lane & 3) == 0) {
            const int r0 = wr * 32 + mf * 16 + (lane >> 2);
            part_sum[r0 * 8 + wc] = s0;       part_sq[r0 * 8 + wc] = q0;
            part_sum[(r0 + 8) * 8 + wc] = s1; part_sq[(r0 + 8) * 8 + wc] = q1;
        }
    }
    __syncthreads();
    if (tid < 64) {
        float s = 0.f, q = 0.f;
#pragma unroll
        for (int w = 0; w < 8; w++) { s += part_sum[tid * 8 + w]; q += part_sq[tid * 8 + w]; }
        const float mean = s * (1.0f / 512.0f);
        const float var  = q * (1.0f / 512.0f) - mean * mean;
        stats[tid * 2] = mean;
        stats[tid * 2 + 1] = rsqrtf(var + LN_EPS);
    }
    __syncthreads();

#pragma unroll
    for (int mf = 0; mf < 2; mf++) {
        const int r0 = wr * 32 + mf * 16 + (lane >> 2), r1 = r0 + 8;
        const float m0 = stats[r0 * 2], rs0 = stats[r0 * 2 + 1];
        const float m1 = stats[r1 * 2], rs1 = stats[r1 * 2 + 1];
#pragma unroll
        for (int nf = 0; nf < 8; nf++) {
            const int c = wc * 64 + nf * 8 + ecol;
            const float g0 = vs_g[c], g1 = vs_g[c + 1];
            const float be0 = vs_be[c], be1 = vs_be[c + 1];
            float2 y0 = make_float2(tanhf((acc[mf][nf][0] - m0) * rs0 * g0 + be0),
                                    tanhf((acc[mf][nf][1] - m0) * rs0 * g1 + be1));
            float2 y1 = make_float2(tanhf((acc[mf][nf][2] - m1) * rs1 * g0 + be0),
                                    tanhf((acc[mf][nf][3] - m1) * rs1 * g1 + be1));
            *(float2*)(out + (size_t)(bm + r0) * W_DIM + c) = y0;
            *(float2*)(out + (size_t)(bm + r1) * W_DIM + c) = y1;
        }
    }
}

// ---------------------------------------------------------------------------
extern "C" void kernel_launch(void* const* d_in, const int* in_sizes, int n_in,
                              void* d_out, int out_size) {
    const float* inputs     = (const float*)d_in[0];
    const float* centers    = (const float*)d_in[1];
    const float* log_scales = (const float*)d_in[2];
    const float* W_mix      = (const float*)d_in[3];
    const float* b_mix      = (const float*)d_in[4];
    const float* ln_gamma   = (const float*)d_in[5];
    const float* ln_beta    = (const float*)d_in[6];
    float* out = (float*)d_out;

    cudaFuncSetAttribute(gemm1_rbf, cudaFuncAttributeMaxDynamicSharedMemorySize, G1_SMEM);
    cudaFuncSetAttribute(gemm2_ln,  cudaFuncAttributeMaxDynamicSharedMemorySize, (int)G2_SMEM);

    conv_x<<<B_ROWS / 8, 256>>>(inputs);
    conv_cw<<<128, 256>>>(centers, log_scales, W_mix);
    gemm1_rbf<<<dim3(G_DIM / 128, B_ROWS / 128), 256, G1_SMEM>>>();
    gemm2_ln<<<B_ROWS / 64, 512, G2_SMEM>>>(b_mix, ln_gamma, ln_beta, out);
}